// round 12
// baseline (speedup 1.0000x reference)
#include <cuda_runtime.h>
#include <cstdint>

#define NUM_CLASSES 80
#define PRE_NMS_K   400
#define MAX_BOXES   200
#define NMS_THRESH  0.6f
#define BATCH       8
#define NANCH       16128   // 64*64*3 + 32*32*3 + 16*16*3
#define FLAT_K      (NUM_CLASSES * PRE_NMS_K)   // 32000
#define C5          85
#define NWORD       13      // ceil(400/32)
#define CAND_CAP    2048
#define T0_BITS     0x3F051EB8u   // 0.52f: conservative fixed candidate threshold
#define FH_BINS     4096          // per-image final histogram (mantissa bits [22:11])
#define FSEG        16            // fcompact blocks per image

typedef unsigned long long ull;

// ---- device scratch ----
__device__ float g_boxes[BATCH * NANCH * 4];
__device__ float g_scores[BATCH * NUM_CLASSES * NANCH];         // fallback path
__device__ float g_kept_scores[BATCH * NUM_CLASSES * PRE_NMS_K];
__device__ unsigned g_kept_idx[BATCH * NUM_CLASSES * PRE_NMS_K];
__device__ unsigned g_cand_cnt[BATCH * NUM_CLASSES];
__device__ ull g_cand[BATCH * NUM_CLASSES * CAND_CAP];
__device__ unsigned g_fhist[BATCH * FH_BINS];                   // per-image kept-score histogram
__device__ unsigned g_final_T[BATCH];                           // per-image threshold (0 = fallback)
__device__ unsigned g_fcand_cnt[BATCH];
__device__ ull g_fcand[BATCH * CAND_CAP];

__device__ __forceinline__ float sigmoidf(float x) {
    return 1.0f / (1.0f + expf(-x));
}

__device__ __forceinline__ int fh_bin(unsigned k) {
    return (k >= 0x3F000000u && k < 0x3F800000u) ? (int)((k >> 11) & 0xFFFu) : 0;
}

// ============================================================
// Kernel 0: reset counters + final histogram
// ============================================================
__global__ void reset_kernel()
{
    int i = blockIdx.x * blockDim.x + threadIdx.x;
    if (i < BATCH * NUM_CLASSES) g_cand_cnt[i] = 0u;
    if (i < BATCH * FH_BINS) g_fhist[i] = 0u;
    if (i < BATCH) g_fcand_cnt[i] = 0u;
}

// ============================================================
// Kernel 1: decode + candidate generation (segment-aggregated).
// ============================================================
__global__ __launch_bounds__(256) void decode_kernel(
    const float* __restrict__ p3, const float* __restrict__ p4, const float* __restrict__ p5,
    const float* __restrict__ a3, const float* __restrict__ a4, const float* __restrict__ a5)
{
    __shared__ float4 tile4[64 * C5 / 4];
    __shared__ float s_obj[64];
    float* tile = (float*)tile4;

    int tid = threadIdx.x;
    int lane = tid & 31;
    int blk = blockIdx.x;
    int b  = blk / (NANCH / 64);
    int n0 = (blk % (NANCH / 64)) * 64;

    const float* p; const float* anc;
    int HW; float stride, sxy; int base;
    if (n0 < 12288)      { p = p3; anc = a3; HW = 64; stride = 8.0f;  sxy = 1.20f; base = 0; }
    else if (n0 < 15360) { p = p4; anc = a4; HW = 32; stride = 16.0f; sxy = 1.10f; base = 12288; }
    else                 { p = p5; anc = a5; HW = 16; stride = 32.0f; sxy = 1.05f; base = 15360; }

    int loc0 = n0 - base;
    const float4* src4 = (const float4*)(p + ((size_t)b * HW * HW * 3 + loc0) * C5);

    for (int i = tid; i < 64 * C5 / 4; i += 256) tile4[i] = src4[i];
    __syncthreads();

    if (tid < 64) {
        int loc = loc0 + tid;
        int a  = loc % 3;
        int hw = loc / 3;
        int w  = hw % HW;
        int h  = hw / HW;
        const float* r = &tile[tid * C5];

        float invHW = 1.0f / (float)HW;
        float sx = sigmoidf(r[0]);
        float sy = sigmoidf(r[1]);
        float x = (sx * sxy - 0.5f * (sxy - 1.0f) + (float)w) * invHW;
        float y = (sy * sxy - 0.5f * (sxy - 1.0f) + (float)h) * invHW;

        float denom = 1.0f / ((float)HW * stride);
        float bw = expf(r[2]) * anc[a * 2 + 0] * denom;
        float bh = expf(r[3]) * anc[a * 2 + 1] * denom;

        float y1 = fminf(fmaxf(y - 0.5f * bh, 0.0f), 1.0f);
        float x1 = fminf(fmaxf(x - 0.5f * bw, 0.0f), 1.0f);
        float y2 = fminf(fmaxf(y + 0.5f * bh, 0.0f), 1.0f);
        float x2 = fminf(fmaxf(x + 0.5f * bw, 0.0f), 1.0f);

        ((float4*)g_boxes)[(size_t)b * NANCH + n0 + tid] = make_float4(y1, x1, y2, x2);
        s_obj[tid] = sigmoidf(r[4]);
    }
    __syncthreads();

    size_t sbase = (size_t)b * NUM_CLASSES * NANCH + n0;
    for (int i = tid; i < 64 * NUM_CLASSES / 4; i += 256) {
        int c  = i >> 4;
        int a0 = (i & 15) * 4;
        float4 v;
        v.x = sigmoidf(tile[(a0 + 0) * C5 + 5 + c]) * s_obj[a0 + 0];
        v.y = sigmoidf(tile[(a0 + 1) * C5 + 5 + c]) * s_obj[a0 + 1];
        v.z = sigmoidf(tile[(a0 + 2) * C5 + 5 + c]) * s_obj[a0 + 2];
        v.w = sigmoidf(tile[(a0 + 3) * C5 + 5 + c]) * s_obj[a0 + 3];
        *(float4*)(g_scores + sbase + (size_t)c * NANCH + a0) = v;

        unsigned kb[4] = {__float_as_uint(v.x), __float_as_uint(v.y),
                          __float_as_uint(v.z), __float_as_uint(v.w)};
        int h = (kb[0] >= T0_BITS) + (kb[1] >= T0_BITS) +
                (kb[2] >= T0_BITS) + (kb[3] >= T0_BITS);

        int pre = h;
#pragma unroll
        for (int off = 1; off < 16; off <<= 1) {
            int t2 = __shfl_up_sync(0xFFFFFFFFu, pre, off);
            if ((lane & 15) >= off) pre += t2;
        }
        int segtop = (lane & ~15) | 15;
        unsigned bbase = 0u;
        int bcc = b * NUM_CLASSES + c;
        if (lane == segtop && pre > 0)
            bbase = atomicAdd(&g_cand_cnt[bcc], (unsigned)pre);
        bbase = __shfl_sync(0xFFFFFFFFu, bbase, segtop);
        unsigned pos = bbase + (unsigned)(pre - h);
        if (h) {
#pragma unroll
            for (int e = 0; e < 4; e++) {
                if (kb[e] >= T0_BITS) {
                    if (pos < CAND_CAP) {
                        unsigned idx = (unsigned)(n0 + a0 + e);
                        g_cand[(size_t)bcc * CAND_CAP + pos] =
                            ((ull)kb[e] << 32) | (ull)(0xFFFFFFFFu - idx);
                    }
                    pos++;
                }
            }
        }
    }
}

// ============================================================
// Exact adaptive radix threshold over global scores (fallback).
// Stride generalized to blockDim.x.
// ============================================================
struct RadixState { unsigned prefix, T; int rem, done; };

__device__ unsigned radix_thresh(const float4* __restrict__ sc4, int n4, int K, int cap,
                                 unsigned* hist /*2048*/, RadixState* st)
{
    int tid = threadIdx.x;
    int lane = tid & 31;
    int nt = blockDim.x;
    if (tid == 0) { st->prefix = 0u; st->rem = K; st->done = 0; }

    for (int lvl = 0; lvl < 3; lvl++) {
        const int shift = (lvl == 0) ? 20 : ((lvl == 1) ? 10 : 0);
        const int bins  = (lvl == 0) ? 2048 : 1024;
        for (int i = tid; i < bins; i += nt) hist[i] = 0u;
        __syncthreads();
        unsigned pref = st->prefix;
        for (int i = tid; i < n4; i += nt) {
            float4 v = sc4[i];
            unsigned kk[4] = {__float_as_uint(v.x), __float_as_uint(v.y),
                              __float_as_uint(v.z), __float_as_uint(v.w)};
#pragma unroll
            for (int e = 0; e < 4; e++) {
                unsigned k = kk[e];
                if (lvl == 0 || (k >> (shift + 10)) == pref)
                    atomicAdd(&hist[(k >> shift) & (bins - 1)], 1u);
            }
        }
        __syncthreads();
        if (tid < 32) {
            int per = bins / 32;
            int hi = bins - 1 - lane * per;
            unsigned s = 0;
            for (int e = 0; e < per; e++) s += hist[hi - e];
            unsigned inc = s;
#pragma unroll
            for (int off = 1; off < 32; off <<= 1) {
                unsigned t2 = __shfl_up_sync(0xFFFFFFFFu, inc, off);
                if (lane >= off) inc += t2;
            }
            unsigned excl = inc - s;
            int rem = st->rem;
            bool has = (excl < (unsigned)rem) && ((unsigned)rem <= inc);
            unsigned ball = __ballot_sync(0xFFFFFFFFu, has);
            int ldr = (ball == 0u) ? 31 : (__ffs(ball) - 1);
            if (lane == ldr) {
                unsigned cum = excl;
                int bkt = hi - per + 1;
                unsigned bcount = 0u;
                for (int e = 0; e < per; e++) {
                    unsigned h = hist[hi - e];
                    if (cum + h >= (unsigned)rem) { bkt = hi - e; bcount = h; break; }
                    cum += h;
                }
                unsigned newpref = (lvl == 0) ? (unsigned)bkt
                                              : ((pref << 10) | (unsigned)bkt);
                int tot = (K - rem) + (int)cum + (int)bcount;
                if (tot <= cap || lvl == 2) {
                    st->T = newpref << shift;
                    st->done = 1;
                } else {
                    st->prefix = newpref;
                    st->rem = rem - (int)cum;
                }
            }
        }
        __syncthreads();
        if (st->done) break;
    }
    return st->T;
}

// ============================================================
// Compaction from global scores into smem keys.
// ============================================================
__device__ int compact_pass(const float4* __restrict__ sc4, int n4, unsigned T,
                            ull* cand, int cap, int* s_cnt)
{
    int tid = threadIdx.x;
    int lane = tid & 31;
    int nt = blockDim.x;
    if (tid == 0) *s_cnt = 0;
    __syncthreads();
    int iters = (n4 + nt - 1) / nt;
    for (int it = 0; it < iters; it++) {
        int i = it * nt + tid;
        unsigned kk[4] = {0u, 0u, 0u, 0u};
        bool tk[4] = {false, false, false, false};
        if (i < n4) {
            float4 v = sc4[i];
            kk[0] = __float_as_uint(v.x); kk[1] = __float_as_uint(v.y);
            kk[2] = __float_as_uint(v.z); kk[3] = __float_as_uint(v.w);
#pragma unroll
            for (int e = 0; e < 4; e++)
                tk[e] = (T > 0u) ? (kk[e] >= T) : (kk[e] > 0u);
        }
        int c = (int)tk[0] + (int)tk[1] + (int)tk[2] + (int)tk[3];
        int pre = c;
#pragma unroll
        for (int off = 1; off < 32; off <<= 1) {
            int t2 = __shfl_up_sync(0xFFFFFFFFu, pre, off);
            if (lane >= off) pre += t2;
        }
        int base;
        if (lane == 31) base = atomicAdd(s_cnt, pre);
        base = __shfl_sync(0xFFFFFFFFu, base, 31);
        int pos = base + pre - c;
#pragma unroll
        for (int e = 0; e < 4; e++) {
            if (tk[e]) {
                if (pos < cap)
                    cand[pos] = ((ull)kk[e] << 32) |
                                (ull)(0xFFFFFFFFu - (unsigned)(i * 4 + e));
                pos++;
            }
        }
    }
    __syncthreads();
    return *s_cnt;
}

// ============================================================
// Exact u64-key selection over cnt smem keys (keys unique).
// ============================================================
struct SelState { ull pref, T; int above, done; };

__device__ ull select_key(const ull* __restrict__ cand, int cnt, int Klo, int Khi,
                          unsigned* hist /*1024*/, SelState* st)
{
    int tid = threadIdx.x;
    int lane = tid & 31;
    int nt = blockDim.x;
    if (tid == 0) { st->pref = 0ull; st->above = 0; st->done = 0; st->T = 0ull; }
    __syncthreads();
    for (int lvl = 0; lvl < 7; lvl++) {
        const int shift = (lvl < 6) ? (53 - 10 * lvl) : 0;
        const int width = (lvl < 6) ? 10 : 3;
        const unsigned mask = (1u << width) - 1u;
        for (int i = tid; i < 1024; i += nt) hist[i] = 0u;
        __syncthreads();
        ull pref = st->pref;
        for (int i = tid; i < cnt; i += nt) {
            ull k = cand[i];
            if (lvl == 0 || (k >> (shift + width)) == pref)
                atomicAdd(&hist[(unsigned)(k >> shift) & mask], 1u);
        }
        __syncthreads();
        if (tid < 32) {
            int hi = 1023 - lane * 32;
            unsigned s = 0;
            for (int e = 0; e < 32; e++) s += hist[hi - e];
            unsigned inc = s;
#pragma unroll
            for (int off = 1; off < 32; off <<= 1) {
                unsigned t2 = __shfl_up_sync(0xFFFFFFFFu, inc, off);
                if (lane >= off) inc += t2;
            }
            unsigned excl = inc - s;
            int above = st->above;
            bool has = (above + (int)excl < Klo) && (above + (int)inc >= Klo);
            unsigned ball = __ballot_sync(0xFFFFFFFFu, has);
            if (ball != 0u && lane == (__ffs(ball) - 1)) {
                unsigned cum = excl;
                for (int e = 0; e < 32; e++) {
                    unsigned h = hist[hi - e];
                    if (above + (int)(cum + h) >= Klo) {
                        int tot = above + (int)(cum + h);
                        if (tot <= Khi) {
                            st->T = ((pref << width) | (ull)(unsigned)(hi - e)) << shift;
                            st->done = 1;
                        } else {
                            st->pref = (pref << width) | (ull)(unsigned)(hi - e);
                            st->above = above + (int)cum;
                        }
                        break;
                    }
                    cum += h;
                }
            }
        }
        __syncthreads();
        if (st->done) break;
    }
    return st->T;
}

// warp-aggregated smem->smem compaction of keys >= Tk
__device__ int compact_keys(const ull* __restrict__ src, int cnt, ull Tk,
                            ull* dst, int cap, int* s_cnt)
{
    int tid = threadIdx.x;
    int lane = tid & 31;
    int nt = blockDim.x;
    if (tid == 0) *s_cnt = 0;
    __syncthreads();
    int iters = (cnt + nt - 1) / nt;
    for (int it = 0; it < iters; it++) {
        int i = it * nt + tid;
        bool take = (i < cnt) && (src[i] >= Tk) && (src[i] != 0ull);
        unsigned ball = __ballot_sync(0xFFFFFFFFu, take);
        if (ball) {
            int leader = __ffs(ball) - 1;
            int base;
            if (lane == leader) base = atomicAdd(s_cnt, __popc(ball));
            base = __shfl_sync(0xFFFFFFFFu, base, leader);
            if (take) {
                int pos = base + __popc(ball & ((1u << lane) - 1u));
                if (pos < cap) dst[pos] = src[i];
            }
        }
    }
    __syncthreads();
    return *s_cnt;
}

// descending bitonic sort, pair-index form
template <int SIZE>
__device__ void bitonic_desc(ull* a)
{
    int tid = threadIdx.x;
    int nt = blockDim.x;
    for (int k = 2; k <= SIZE; k <<= 1) {
        for (int j = k >> 1; j > 0; j >>= 1) {
            __syncthreads();
            for (int p = tid; p < SIZE / 2; p += nt) {
                int i   = ((p & ~(j - 1)) << 1) | (p & (j - 1));
                int ixj = i | j;
                bool seg = (i & k) == 0;
                ull x = a[i], y = a[ixj];
                if (seg ? (x < y) : (x > y)) { a[i] = y; a[ixj] = x; }
            }
        }
    }
    __syncthreads();
}

// ============================================================
// Kernel 2: per (b, class) top-400 + greedy NMS (+ final hist)
// 512 threads.
// ============================================================
__global__ __launch_bounds__(512) void percls_kernel()
{
    __shared__ union {
        struct {
            ull cand[CAND_CAP];
            unsigned hist[1024];
        } ph1;
        unsigned mat[PRE_NMS_K][NWORD];
    } u;
    __shared__ RadixState rst;
    __shared__ SelState sst;
    __shared__ ull cand2[512];
    __shared__ int s_cnt;
    __shared__ float bx0[PRE_NMS_K], bx1[PRE_NMS_K], bx2[PRE_NMS_K], bx3[PRE_NMS_K], ar[PRE_NMS_K];
    __shared__ unsigned nzmask[NWORD];
    __shared__ unsigned keepw[NWORD];

    int tid = threadIdx.x;
    const int NT = 512;
    int bc = blockIdx.x;
    int b = bc / NUM_CLASSES;

    int cnt = (int)g_cand_cnt[bc];
    if (cnt >= PRE_NMS_K && cnt <= CAND_CAP) {
        const ull* src = g_cand + (size_t)bc * CAND_CAP;
        for (int i = tid; i < cnt; i += NT) u.ph1.cand[i] = src[i];
        __syncthreads();
    } else {
        const float4* sc4 = (const float4*)(g_scores + (size_t)bc * NANCH);
        const int n4 = NANCH / 4;
        unsigned T = radix_thresh(sc4, n4, PRE_NMS_K, 1024, (unsigned*)u.ph1.cand, &rst);
        cnt = compact_pass(sc4, n4, T, u.ph1.cand, 1024, &s_cnt);
        cnt = min(cnt, 1024);
    }

    ull Tk = 0ull;
    if (cnt > 512)
        Tk = select_key(u.ph1.cand, cnt, PRE_NMS_K, 512, u.ph1.hist, &sst);
    cnt = compact_keys(u.ph1.cand, cnt, Tk, cand2, 512, &s_cnt);
    cnt = min(cnt, 512);
    for (int i = tid; i < 512; i += NT) if (i >= cnt) cand2[i] = 0ULL;
    bitonic_desc<512>(cand2);

    const float4* gb4 = (const float4*)g_boxes + (size_t)b * NANCH;
    for (int t = tid; t < PRE_NMS_K; t += NT) {
        unsigned idx = 0xFFFFFFFFu - (unsigned)(cand2[t] & 0xFFFFFFFFull);
        float4 bp = gb4[idx];
        bx0[t] = bp.x; bx1[t] = bp.y; bx2[t] = bp.z; bx3[t] = bp.w;
        ar[t] = (bp.z - bp.x) * (bp.w - bp.y);
    }
    if (tid < NWORD) nzmask[tid] = 0u;
    __syncthreads();

    for (int p = tid; p < (PRE_NMS_K / 4) * NWORD; p += NT) {
        int i4 = p % (PRE_NMS_K / 4);
        int w  = p / (PRE_NMS_K / 4);
        int i0 = i4 * 4;
        int jbase = w * 32;
        unsigned bits[4] = {0u, 0u, 0u, 0u};
        if (jbase + 31 > i0) {
            float ry1[4], rx1[4], ry2[4], rx2[4], rar[4];
#pragma unroll
            for (int r = 0; r < 4; r++) {
                ry1[r] = bx0[i0 + r]; rx1[r] = bx1[i0 + r];
                ry2[r] = bx2[i0 + r]; rx2[r] = bx3[i0 + r];
                rar[r] = ar[i0 + r];
            }
            int jend = min(32, PRE_NMS_K - jbase);
            for (int jj = 0; jj < jend; jj++) {
                int j = jbase + jj;
                float jy1 = bx0[j], jx1 = bx1[j], jy2 = bx2[j], jx2 = bx3[j], jar = ar[j];
#pragma unroll
                for (int r = 0; r < 4; r++) {
                    if (j > i0 + r) {
                        float hh = fmaxf(fminf(ry2[r], jy2) - fmaxf(ry1[r], jy1), 0.0f);
                        float ww = fmaxf(fminf(rx2[r], jx2) - fmaxf(rx1[r], jx1), 0.0f);
                        float inter = hh * ww;
                        float uni = rar[r] + jar - inter;
                        if (inter > NMS_THRESH * fmaxf(uni, 1e-9f)) bits[r] |= (1u << jj);
                    }
                }
            }
        }
#pragma unroll
        for (int r = 0; r < 4; r++) {
            u.mat[i0 + r][w] = bits[r];
            if (bits[r]) atomicOr(&nzmask[(i0 + r) >> 5], 1u << ((i0 + r) & 31));
        }
    }
    __syncthreads();

    if (tid < 32) {
        unsigned kw = (tid < 12) ? 0xFFFFFFFFu : ((tid == 12) ? 0xFFFFu : 0u);
        for (int iw = 0; iw < NWORD; iw++) {
            unsigned done = 0u;
            while (true) {
                unsigned wb = __shfl_sync(0xFFFFFFFFu, kw, iw);
                unsigned act = wb & nzmask[iw] & ~done;
                if (act == 0u) break;
                int bit = __ffs(act) - 1;
                done |= (1u << bit);
                int i = iw * 32 + bit;
                if (tid < NWORD) kw &= ~u.mat[i][tid];
            }
        }
        if (tid < NWORD) keepw[tid] = kw;
    }
    __syncthreads();

    float* ks = g_kept_scores + (size_t)bc * PRE_NMS_K;
    unsigned* ki = g_kept_idx + (size_t)bc * PRE_NMS_K;
    for (int t = tid; t < PRE_NMS_K; t += NT) {
        ull key = cand2[t];
        unsigned kbits = (unsigned)(key >> 32);
        float v = __uint_as_float(kbits);
        int kept = (keepw[t >> 5] >> (t & 31)) & 1;
        bool live = kept && v > 0.0f;
        ks[t] = live ? v : 0.0f;
        ki[t] = 0xFFFFFFFFu - (unsigned)(key & 0xFFFFFFFFull);
        if (live) atomicAdd(&g_fhist[b * FH_BINS + fh_bin(kbits)], 1u);
    }
}

// ============================================================
// Kernel 3a: per-image rank-200 threshold from exact histogram
// grid = BATCH, 32 threads
// ============================================================
__global__ __launch_bounds__(32) void thresh_kernel()
{
    int lane = threadIdx.x;
    int b = blockIdx.x;
    const unsigned* fh = g_fhist + b * FH_BINS;

    int per = FH_BINS / 32;                   // 128 bins per lane
    int hi = FH_BINS - 1 - lane * per;
    unsigned s = 0;
    for (int e = 0; e < per; e++) { int bin = hi - e; if (bin >= 1) s += fh[bin]; }
    unsigned inc = s;
#pragma unroll
    for (int off = 1; off < 32; off <<= 1) {
        unsigned t2 = __shfl_up_sync(0xFFFFFFFFu, inc, off);
        if (lane >= off) inc += t2;
    }
    unsigned excl = inc - s;
    bool has = (excl < (unsigned)MAX_BOXES) && (inc >= (unsigned)MAX_BOXES);
    unsigned ball = __ballot_sync(0xFFFFFFFFu, has);
    if (lane == 0 && ball == 0u) g_final_T[b] = 0u;   // fallback
    if (ball != 0u && lane == (__ffs(ball) - 1)) {
        unsigned T = 0u;
        unsigned cum = excl;
        for (int e = 0; e < per; e++) {
            int bin = hi - e;
            if (bin < 1) break;
            unsigned h = fh[bin];
            if (cum + h >= (unsigned)MAX_BOXES) {
                if (cum + h <= (unsigned)CAND_CAP)
                    T = 0x3F000000u | ((unsigned)bin << 11);
                break;
            }
            cum += h;
        }
        g_final_T[b] = T;
    }
}

// ============================================================
// Kernel 3b: parallel per-image compaction of kept scores >= T
// grid = BATCH * FSEG, 256 threads
// ============================================================
__global__ __launch_bounds__(256) void fcompact_kernel()
{
    int tid = threadIdx.x;
    int lane = tid & 31;
    int blk = blockIdx.x;
    int b = blk / FSEG;
    int seg = blk % FSEG;
    unsigned T = g_final_T[b];
    if (T == 0u) return;                      // fallback handled in foutput

    const int n4 = FLAT_K / 4;                // 8000
    const int per = n4 / FSEG;                // 500
    const float4* sc4 = (const float4*)(g_kept_scores + (size_t)b * FLAT_K) + seg * per;
    int ibase = seg * per;

    for (int i = tid; i < per; i += 256) {
        float4 v = sc4[i];
        unsigned kk[4] = {__float_as_uint(v.x), __float_as_uint(v.y),
                          __float_as_uint(v.z), __float_as_uint(v.w)};
        bool tk[4];
#pragma unroll
        for (int e = 0; e < 4; e++) tk[e] = kk[e] >= T;
        int c = (int)tk[0] + (int)tk[1] + (int)tk[2] + (int)tk[3];
        unsigned ball = __ballot_sync(0xFFFFFFFFu, c > 0);
        if (__any_sync(0xFFFFFFFFu, c > 0)) {
            int pre = c;
#pragma unroll
            for (int off = 1; off < 32; off <<= 1) {
                int t2 = __shfl_up_sync(0xFFFFFFFFu, pre, off);
                if (lane >= off) pre += t2;
            }
            unsigned base;
            if (lane == 31 && pre > 0) base = atomicAdd(&g_fcand_cnt[b], (unsigned)pre);
            base = __shfl_sync(0xFFFFFFFFu, base, 31);
            unsigned pos = base + (unsigned)(pre - c);
#pragma unroll
            for (int e = 0; e < 4; e++) {
                if (tk[e]) {
                    if (pos < CAND_CAP) {
                        unsigned flat = (unsigned)((ibase + i) * 4 + e);
                        g_fcand[(size_t)b * CAND_CAP + pos] =
                            ((ull)kk[e] << 32) | (ull)(0xFFFFFFFFu - flat);
                    }
                    pos++;
                }
            }
        }
        (void)ball;
    }
}

// ============================================================
// Kernel 3c: per-image select + sort + output
// grid = BATCH, 256 threads
// out layout (float32): bbox[8][200][4] | conf[8][200] | cls[8][200] | num[8]
// ============================================================
__global__ __launch_bounds__(256) void foutput_kernel(float* __restrict__ out)
{
    __shared__ ull cand[CAND_CAP];            // 16 KB
    __shared__ unsigned shist[2048];          // select_key (1024) / radix fallback (2048)
    __shared__ ull cand2[512];
    __shared__ RadixState rst;
    __shared__ SelState sst;
    __shared__ int s_cnt, s_nval;

    int tid = threadIdx.x;
    int b = blockIdx.x;
    unsigned T = g_final_T[b];
    int cnt;

    if (T != 0u) {
        cnt = min((int)g_fcand_cnt[b], CAND_CAP);
        const ull* src = g_fcand + (size_t)b * CAND_CAP;
        for (int i = tid; i < cnt; i += 256) cand[i] = src[i];
        __syncthreads();
    } else {
        // exact fallback: scan kept scores
        const float4* sc4 = (const float4*)(g_kept_scores + (size_t)b * FLAT_K);
        const int n4 = FLAT_K / 4;
        unsigned Tf = radix_thresh(sc4, n4, MAX_BOXES, 512, shist, &rst);
        cnt = compact_pass(sc4, n4, Tf, cand, 512, &s_cnt);
        cnt = min(cnt, 512);
    }

    ull Tk = 0ull;
    if (cnt > 512)
        Tk = select_key(cand, cnt, MAX_BOXES, 512, shist, &sst);
    cnt = compact_keys(cand, cnt, Tk, cand2, 512, &s_cnt);
    cnt = min(cnt, 512);
    for (int i = tid; i < 512; i += 256) if (i >= cnt) cand2[i] = 0ULL;
    bitonic_desc<512>(cand2);

    if (tid == 0) s_nval = 0;
    __syncthreads();

    const unsigned* ki = g_kept_idx + (size_t)b * FLAT_K;
    const float4* gb4 = (const float4*)g_boxes + (size_t)b * NANCH;
    for (int t = tid; t < MAX_BOXES; t += 256) {
        ull e = cand2[t];
        float v = __uint_as_float((unsigned)(e >> 32));
        bool valid = v > 0.0f;
        unsigned flat = 0xFFFFFFFFu - (unsigned)(e & 0xFFFFFFFFull);
        float4 bb = make_float4(0.f, 0.f, 0.f, 0.f);
        float clsf = 0.f;
        if (valid) {
            bb = gb4[ki[flat]];
            clsf = (float)(flat / PRE_NMS_K);
            atomicAdd(&s_nval, 1);
        }
        int o = b * MAX_BOXES + t;
        ((float4*)out)[o] = bb;
        out[BATCH * MAX_BOXES * 4 + o] = v;
        out[BATCH * MAX_BOXES * 4 + BATCH * MAX_BOXES + o] = clsf;
    }
    __syncthreads();
    if (tid == 0)
        out[BATCH * MAX_BOXES * 4 + 2 * BATCH * MAX_BOXES + b] = (float)s_nval;
}

// ============================================================
extern "C" void kernel_launch(void* const* d_in, const int* in_sizes, int n_in,
                              void* d_out, int out_size)
{
    const float* p3 = (const float*)d_in[0];
    const float* p4 = (const float*)d_in[1];
    const float* p5 = (const float*)d_in[2];
    const float* a3 = (const float*)d_in[3];
    const float* a4 = (const float*)d_in[4];
    const float* a5 = (const float*)d_in[5];
    float* out = (float*)d_out;

    reset_kernel<<<(BATCH * FH_BINS + 255) / 256, 256>>>();
    decode_kernel<<<BATCH * (NANCH / 64), 256>>>(p3, p4, p5, a3, a4, a5);
    percls_kernel<<<BATCH * NUM_CLASSES, 512>>>();
    thresh_kernel<<<BATCH, 32>>>();
    fcompact_kernel<<<BATCH * FSEG, 256>>>();
    foutput_kernel<<<BATCH, 256>>>(out);
}

// round 13
// speedup vs baseline: 1.0913x; 1.0913x over previous
#include <cuda_runtime.h>
#include <cstdint>

#define NUM_CLASSES 80
#define PRE_NMS_K   400
#define MAX_BOXES   200
#define NMS_THRESH  0.6f
#define BATCH       8
#define NANCH       16128   // 64*64*3 + 32*32*3 + 16*16*3
#define FLAT_K      (NUM_CLASSES * PRE_NMS_K)   // 32000
#define C5          85
#define NWORD       13      // ceil(400/32)
#define CAND_CAP    2048
#define T0_BITS     0x3F051EB8u   // 0.52f: conservative fixed candidate threshold
#define FH_BINS     4096          // per-image final histogram (mantissa bits [22:11])
#define FSEG        16            // fcompact blocks per image

typedef unsigned long long ull;

// ---- device scratch ----
__device__ float g_boxes[BATCH * NANCH * 4];
__device__ float g_scores[BATCH * NUM_CLASSES * NANCH];         // fallback path
__device__ float g_kept_scores[BATCH * NUM_CLASSES * PRE_NMS_K];
__device__ unsigned g_kept_idx[BATCH * NUM_CLASSES * PRE_NMS_K];
__device__ unsigned g_cand_cnt[BATCH * NUM_CLASSES];
__device__ ull g_cand[BATCH * NUM_CLASSES * CAND_CAP];
__device__ unsigned g_fhist[BATCH * FH_BINS];                   // per-image kept-score histogram
__device__ unsigned g_final_T[BATCH];                           // per-image threshold (0 = fallback)
__device__ unsigned g_fcand_cnt[BATCH];
__device__ ull g_fcand[BATCH * CAND_CAP];

__device__ __forceinline__ float sigmoidf(float x) {
    return 1.0f / (1.0f + expf(-x));
}

__device__ __forceinline__ int fh_bin(unsigned k) {
    return (k >= 0x3F000000u && k < 0x3F800000u) ? (int)((k >> 11) & 0xFFFu) : 0;
}

// ============================================================
// Kernel 0: reset counters + final histogram
// ============================================================
__global__ void reset_kernel()
{
    int i = blockIdx.x * blockDim.x + threadIdx.x;
    if (i < BATCH * NUM_CLASSES) g_cand_cnt[i] = 0u;
    if (i < BATCH * FH_BINS) g_fhist[i] = 0u;
    if (i < BATCH) g_fcand_cnt[i] = 0u;
}

// ============================================================
// Kernel 1: decode + candidate generation (segment-aggregated).
// ============================================================
__global__ __launch_bounds__(256) void decode_kernel(
    const float* __restrict__ p3, const float* __restrict__ p4, const float* __restrict__ p5,
    const float* __restrict__ a3, const float* __restrict__ a4, const float* __restrict__ a5)
{
    __shared__ float4 tile4[64 * C5 / 4];
    __shared__ float s_obj[64];
    float* tile = (float*)tile4;

    int tid = threadIdx.x;
    int lane = tid & 31;
    int blk = blockIdx.x;
    int b  = blk / (NANCH / 64);
    int n0 = (blk % (NANCH / 64)) * 64;

    const float* p; const float* anc;
    int HW; float stride, sxy; int base;
    if (n0 < 12288)      { p = p3; anc = a3; HW = 64; stride = 8.0f;  sxy = 1.20f; base = 0; }
    else if (n0 < 15360) { p = p4; anc = a4; HW = 32; stride = 16.0f; sxy = 1.10f; base = 12288; }
    else                 { p = p5; anc = a5; HW = 16; stride = 32.0f; sxy = 1.05f; base = 15360; }

    int loc0 = n0 - base;
    const float4* src4 = (const float4*)(p + ((size_t)b * HW * HW * 3 + loc0) * C5);

    for (int i = tid; i < 64 * C5 / 4; i += 256) tile4[i] = src4[i];
    __syncthreads();

    if (tid < 64) {
        int loc = loc0 + tid;
        int a  = loc % 3;
        int hw = loc / 3;
        int w  = hw % HW;
        int h  = hw / HW;
        const float* r = &tile[tid * C5];

        float invHW = 1.0f / (float)HW;
        float sx = sigmoidf(r[0]);
        float sy = sigmoidf(r[1]);
        float x = (sx * sxy - 0.5f * (sxy - 1.0f) + (float)w) * invHW;
        float y = (sy * sxy - 0.5f * (sxy - 1.0f) + (float)h) * invHW;

        float denom = 1.0f / ((float)HW * stride);
        float bw = expf(r[2]) * anc[a * 2 + 0] * denom;
        float bh = expf(r[3]) * anc[a * 2 + 1] * denom;

        float y1 = fminf(fmaxf(y - 0.5f * bh, 0.0f), 1.0f);
        float x1 = fminf(fmaxf(x - 0.5f * bw, 0.0f), 1.0f);
        float y2 = fminf(fmaxf(y + 0.5f * bh, 0.0f), 1.0f);
        float x2 = fminf(fmaxf(x + 0.5f * bw, 0.0f), 1.0f);

        ((float4*)g_boxes)[(size_t)b * NANCH + n0 + tid] = make_float4(y1, x1, y2, x2);
        s_obj[tid] = sigmoidf(r[4]);
    }
    __syncthreads();

    size_t sbase = (size_t)b * NUM_CLASSES * NANCH + n0;
    for (int i = tid; i < 64 * NUM_CLASSES / 4; i += 256) {
        int c  = i >> 4;
        int a0 = (i & 15) * 4;
        float4 v;
        v.x = sigmoidf(tile[(a0 + 0) * C5 + 5 + c]) * s_obj[a0 + 0];
        v.y = sigmoidf(tile[(a0 + 1) * C5 + 5 + c]) * s_obj[a0 + 1];
        v.z = sigmoidf(tile[(a0 + 2) * C5 + 5 + c]) * s_obj[a0 + 2];
        v.w = sigmoidf(tile[(a0 + 3) * C5 + 5 + c]) * s_obj[a0 + 3];
        *(float4*)(g_scores + sbase + (size_t)c * NANCH + a0) = v;

        unsigned kb[4] = {__float_as_uint(v.x), __float_as_uint(v.y),
                          __float_as_uint(v.z), __float_as_uint(v.w)};
        int h = (kb[0] >= T0_BITS) + (kb[1] >= T0_BITS) +
                (kb[2] >= T0_BITS) + (kb[3] >= T0_BITS);

        int pre = h;
#pragma unroll
        for (int off = 1; off < 16; off <<= 1) {
            int t2 = __shfl_up_sync(0xFFFFFFFFu, pre, off);
            if ((lane & 15) >= off) pre += t2;
        }
        int segtop = (lane & ~15) | 15;
        unsigned bbase = 0u;
        int bcc = b * NUM_CLASSES + c;
        if (lane == segtop && pre > 0)
            bbase = atomicAdd(&g_cand_cnt[bcc], (unsigned)pre);
        bbase = __shfl_sync(0xFFFFFFFFu, bbase, segtop);
        unsigned pos = bbase + (unsigned)(pre - h);
        if (h) {
#pragma unroll
            for (int e = 0; e < 4; e++) {
                if (kb[e] >= T0_BITS) {
                    if (pos < CAND_CAP) {
                        unsigned idx = (unsigned)(n0 + a0 + e);
                        g_cand[(size_t)bcc * CAND_CAP + pos] =
                            ((ull)kb[e] << 32) | (ull)(0xFFFFFFFFu - idx);
                    }
                    pos++;
                }
            }
        }
    }
}

// ============================================================
// Exact adaptive radix threshold over global scores (fallback).
// ============================================================
struct RadixState { unsigned prefix, T; int rem, done; };

__device__ unsigned radix_thresh(const float4* __restrict__ sc4, int n4, int K, int cap,
                                 unsigned* hist /*2048*/, RadixState* st)
{
    int tid = threadIdx.x;
    int lane = tid & 31;
    int nt = blockDim.x;
    if (tid == 0) { st->prefix = 0u; st->rem = K; st->done = 0; }

    for (int lvl = 0; lvl < 3; lvl++) {
        const int shift = (lvl == 0) ? 20 : ((lvl == 1) ? 10 : 0);
        const int bins  = (lvl == 0) ? 2048 : 1024;
        for (int i = tid; i < bins; i += nt) hist[i] = 0u;
        __syncthreads();
        unsigned pref = st->prefix;
        for (int i = tid; i < n4; i += nt) {
            float4 v = sc4[i];
            unsigned kk[4] = {__float_as_uint(v.x), __float_as_uint(v.y),
                              __float_as_uint(v.z), __float_as_uint(v.w)};
#pragma unroll
            for (int e = 0; e < 4; e++) {
                unsigned k = kk[e];
                if (lvl == 0 || (k >> (shift + 10)) == pref)
                    atomicAdd(&hist[(k >> shift) & (bins - 1)], 1u);
            }
        }
        __syncthreads();
        if (tid < 32) {
            int per = bins / 32;
            int hi = bins - 1 - lane * per;
            unsigned s = 0;
            for (int e = 0; e < per; e++) s += hist[hi - e];
            unsigned inc = s;
#pragma unroll
            for (int off = 1; off < 32; off <<= 1) {
                unsigned t2 = __shfl_up_sync(0xFFFFFFFFu, inc, off);
                if (lane >= off) inc += t2;
            }
            unsigned excl = inc - s;
            int rem = st->rem;
            bool has = (excl < (unsigned)rem) && ((unsigned)rem <= inc);
            unsigned ball = __ballot_sync(0xFFFFFFFFu, has);
            int ldr = (ball == 0u) ? 31 : (__ffs(ball) - 1);
            if (lane == ldr) {
                unsigned cum = excl;
                int bkt = hi - per + 1;
                unsigned bcount = 0u;
                for (int e = 0; e < per; e++) {
                    unsigned h = hist[hi - e];
                    if (cum + h >= (unsigned)rem) { bkt = hi - e; bcount = h; break; }
                    cum += h;
                }
                unsigned newpref = (lvl == 0) ? (unsigned)bkt
                                              : ((pref << 10) | (unsigned)bkt);
                int tot = (K - rem) + (int)cum + (int)bcount;
                if (tot <= cap || lvl == 2) {
                    st->T = newpref << shift;
                    st->done = 1;
                } else {
                    st->prefix = newpref;
                    st->rem = rem - (int)cum;
                }
            }
        }
        __syncthreads();
        if (st->done) break;
    }
    return st->T;
}

// ============================================================
// Compaction from global scores into smem keys.
// ============================================================
__device__ int compact_pass(const float4* __restrict__ sc4, int n4, unsigned T,
                            ull* cand, int cap, int* s_cnt)
{
    int tid = threadIdx.x;
    int lane = tid & 31;
    int nt = blockDim.x;
    if (tid == 0) *s_cnt = 0;
    __syncthreads();
    int iters = (n4 + nt - 1) / nt;
    for (int it = 0; it < iters; it++) {
        int i = it * nt + tid;
        unsigned kk[4] = {0u, 0u, 0u, 0u};
        bool tk[4] = {false, false, false, false};
        if (i < n4) {
            float4 v = sc4[i];
            kk[0] = __float_as_uint(v.x); kk[1] = __float_as_uint(v.y);
            kk[2] = __float_as_uint(v.z); kk[3] = __float_as_uint(v.w);
#pragma unroll
            for (int e = 0; e < 4; e++)
                tk[e] = (T > 0u) ? (kk[e] >= T) : (kk[e] > 0u);
        }
        int c = (int)tk[0] + (int)tk[1] + (int)tk[2] + (int)tk[3];
        int pre = c;
#pragma unroll
        for (int off = 1; off < 32; off <<= 1) {
            int t2 = __shfl_up_sync(0xFFFFFFFFu, pre, off);
            if (lane >= off) pre += t2;
        }
        int base;
        if (lane == 31) base = atomicAdd(s_cnt, pre);
        base = __shfl_sync(0xFFFFFFFFu, base, 31);
        int pos = base + pre - c;
#pragma unroll
        for (int e = 0; e < 4; e++) {
            if (tk[e]) {
                if (pos < cap)
                    cand[pos] = ((ull)kk[e] << 32) |
                                (ull)(0xFFFFFFFFu - (unsigned)(i * 4 + e));
                pos++;
            }
        }
    }
    __syncthreads();
    return *s_cnt;
}

// ============================================================
// Exact u64-key selection over cnt smem keys (keys unique).
// ============================================================
struct SelState { ull pref, T; int above, done; };

__device__ ull select_key(const ull* __restrict__ cand, int cnt, int Klo, int Khi,
                          unsigned* hist /*1024*/, SelState* st)
{
    int tid = threadIdx.x;
    int lane = tid & 31;
    int nt = blockDim.x;
    if (tid == 0) { st->pref = 0ull; st->above = 0; st->done = 0; st->T = 0ull; }
    __syncthreads();
    for (int lvl = 0; lvl < 7; lvl++) {
        const int shift = (lvl < 6) ? (53 - 10 * lvl) : 0;
        const int width = (lvl < 6) ? 10 : 3;
        const unsigned mask = (1u << width) - 1u;
        for (int i = tid; i < 1024; i += nt) hist[i] = 0u;
        __syncthreads();
        ull pref = st->pref;
        for (int i = tid; i < cnt; i += nt) {
            ull k = cand[i];
            if (lvl == 0 || (k >> (shift + width)) == pref)
                atomicAdd(&hist[(unsigned)(k >> shift) & mask], 1u);
        }
        __syncthreads();
        if (tid < 32) {
            int hi = 1023 - lane * 32;
            unsigned s = 0;
            for (int e = 0; e < 32; e++) s += hist[hi - e];
            unsigned inc = s;
#pragma unroll
            for (int off = 1; off < 32; off <<= 1) {
                unsigned t2 = __shfl_up_sync(0xFFFFFFFFu, inc, off);
                if (lane >= off) inc += t2;
            }
            unsigned excl = inc - s;
            int above = st->above;
            bool has = (above + (int)excl < Klo) && (above + (int)inc >= Klo);
            unsigned ball = __ballot_sync(0xFFFFFFFFu, has);
            if (ball != 0u && lane == (__ffs(ball) - 1)) {
                unsigned cum = excl;
                for (int e = 0; e < 32; e++) {
                    unsigned h = hist[hi - e];
                    if (above + (int)(cum + h) >= Klo) {
                        int tot = above + (int)(cum + h);
                        if (tot <= Khi) {
                            st->T = ((pref << width) | (ull)(unsigned)(hi - e)) << shift;
                            st->done = 1;
                        } else {
                            st->pref = (pref << width) | (ull)(unsigned)(hi - e);
                            st->above = above + (int)cum;
                        }
                        break;
                    }
                    cum += h;
                }
            }
        }
        __syncthreads();
        if (st->done) break;
    }
    return st->T;
}

// warp-aggregated smem->smem compaction of keys >= Tk
__device__ int compact_keys(const ull* __restrict__ src, int cnt, ull Tk,
                            ull* dst, int cap, int* s_cnt)
{
    int tid = threadIdx.x;
    int lane = tid & 31;
    int nt = blockDim.x;
    if (tid == 0) *s_cnt = 0;
    __syncthreads();
    int iters = (cnt + nt - 1) / nt;
    for (int it = 0; it < iters; it++) {
        int i = it * nt + tid;
        bool take = (i < cnt) && (src[i] >= Tk) && (src[i] != 0ull);
        unsigned ball = __ballot_sync(0xFFFFFFFFu, take);
        if (ball) {
            int leader = __ffs(ball) - 1;
            int base;
            if (lane == leader) base = atomicAdd(s_cnt, __popc(ball));
            base = __shfl_sync(0xFFFFFFFFu, base, leader);
            if (take) {
                int pos = base + __popc(ball & ((1u << lane) - 1u));
                if (pos < cap) dst[pos] = src[i];
            }
        }
    }
    __syncthreads();
    return *s_cnt;
}

// descending bitonic sort, pair-index form
template <int SIZE>
__device__ void bitonic_desc(ull* a)
{
    int tid = threadIdx.x;
    int nt = blockDim.x;
    for (int k = 2; k <= SIZE; k <<= 1) {
        for (int j = k >> 1; j > 0; j >>= 1) {
            __syncthreads();
            for (int p = tid; p < SIZE / 2; p += nt) {
                int i   = ((p & ~(j - 1)) << 1) | (p & (j - 1));
                int ixj = i | j;
                bool seg = (i & k) == 0;
                ull x = a[i], y = a[ixj];
                if (seg ? (x < y) : (x > y)) { a[i] = y; a[ixj] = x; }
            }
        }
    }
    __syncthreads();
}

// ============================================================
// Kernel 2: per (b, class) top-400 + greedy NMS (+ final hist)
// 256 threads (proven best config).
// ============================================================
__global__ __launch_bounds__(256) void percls_kernel()
{
    __shared__ union {
        struct {
            ull cand[CAND_CAP];
            unsigned hist[1024];
        } ph1;
        unsigned mat[PRE_NMS_K][NWORD];
    } u;
    __shared__ RadixState rst;
    __shared__ SelState sst;
    __shared__ ull cand2[512];
    __shared__ int s_cnt;
    __shared__ float bx0[PRE_NMS_K], bx1[PRE_NMS_K], bx2[PRE_NMS_K], bx3[PRE_NMS_K], ar[PRE_NMS_K];
    __shared__ unsigned nzmask[NWORD];
    __shared__ unsigned keepw[NWORD];

    int tid = threadIdx.x;
    const int NT = 256;
    int bc = blockIdx.x;
    int b = bc / NUM_CLASSES;

    int cnt = (int)g_cand_cnt[bc];
    if (cnt >= PRE_NMS_K && cnt <= CAND_CAP) {
        const ull* src = g_cand + (size_t)bc * CAND_CAP;
        for (int i = tid; i < cnt; i += NT) u.ph1.cand[i] = src[i];
        __syncthreads();
    } else {
        const float4* sc4 = (const float4*)(g_scores + (size_t)bc * NANCH);
        const int n4 = NANCH / 4;
        unsigned T = radix_thresh(sc4, n4, PRE_NMS_K, 1024, (unsigned*)u.ph1.cand, &rst);
        cnt = compact_pass(sc4, n4, T, u.ph1.cand, 1024, &s_cnt);
        cnt = min(cnt, 1024);
    }

    ull Tk = 0ull;
    if (cnt > 512)
        Tk = select_key(u.ph1.cand, cnt, PRE_NMS_K, 512, u.ph1.hist, &sst);
    cnt = compact_keys(u.ph1.cand, cnt, Tk, cand2, 512, &s_cnt);
    cnt = min(cnt, 512);
    for (int i = tid; i < 512; i += NT) if (i >= cnt) cand2[i] = 0ULL;
    bitonic_desc<512>(cand2);

    const float4* gb4 = (const float4*)g_boxes + (size_t)b * NANCH;
    for (int t = tid; t < PRE_NMS_K; t += NT) {
        unsigned idx = 0xFFFFFFFFu - (unsigned)(cand2[t] & 0xFFFFFFFFull);
        float4 bp = gb4[idx];
        bx0[t] = bp.x; bx1[t] = bp.y; bx2[t] = bp.z; bx3[t] = bp.w;
        ar[t] = (bp.z - bp.x) * (bp.w - bp.y);
    }
    if (tid < NWORD) nzmask[tid] = 0u;
    __syncthreads();

    for (int p = tid; p < (PRE_NMS_K / 4) * NWORD; p += NT) {
        int i4 = p % (PRE_NMS_K / 4);
        int w  = p / (PRE_NMS_K / 4);
        int i0 = i4 * 4;
        int jbase = w * 32;
        unsigned bits[4] = {0u, 0u, 0u, 0u};
        if (jbase + 31 > i0) {
            float ry1[4], rx1[4], ry2[4], rx2[4], rar[4];
#pragma unroll
            for (int r = 0; r < 4; r++) {
                ry1[r] = bx0[i0 + r]; rx1[r] = bx1[i0 + r];
                ry2[r] = bx2[i0 + r]; rx2[r] = bx3[i0 + r];
                rar[r] = ar[i0 + r];
            }
            int jend = min(32, PRE_NMS_K - jbase);
            for (int jj = 0; jj < jend; jj++) {
                int j = jbase + jj;
                float jy1 = bx0[j], jx1 = bx1[j], jy2 = bx2[j], jx2 = bx3[j], jar = ar[j];
#pragma unroll
                for (int r = 0; r < 4; r++) {
                    if (j > i0 + r) {
                        float hh = fmaxf(fminf(ry2[r], jy2) - fmaxf(ry1[r], jy1), 0.0f);
                        float ww = fmaxf(fminf(rx2[r], jx2) - fmaxf(rx1[r], jx1), 0.0f);
                        float inter = hh * ww;
                        float uni = rar[r] + jar - inter;
                        if (inter > NMS_THRESH * fmaxf(uni, 1e-9f)) bits[r] |= (1u << jj);
                    }
                }
            }
        }
#pragma unroll
        for (int r = 0; r < 4; r++) {
            u.mat[i0 + r][w] = bits[r];
            if (bits[r]) atomicOr(&nzmask[(i0 + r) >> 5], 1u << ((i0 + r) & 31));
        }
    }
    __syncthreads();

    if (tid < 32) {
        unsigned kw = (tid < 12) ? 0xFFFFFFFFu : ((tid == 12) ? 0xFFFFu : 0u);
        for (int iw = 0; iw < NWORD; iw++) {
            unsigned done = 0u;
            while (true) {
                unsigned wb = __shfl_sync(0xFFFFFFFFu, kw, iw);
                unsigned act = wb & nzmask[iw] & ~done;
                if (act == 0u) break;
                int bit = __ffs(act) - 1;
                done |= (1u << bit);
                int i = iw * 32 + bit;
                if (tid < NWORD) kw &= ~u.mat[i][tid];
            }
        }
        if (tid < NWORD) keepw[tid] = kw;
    }
    __syncthreads();

    float* ks = g_kept_scores + (size_t)bc * PRE_NMS_K;
    unsigned* ki = g_kept_idx + (size_t)bc * PRE_NMS_K;
    for (int t = tid; t < PRE_NMS_K; t += NT) {
        ull key = cand2[t];
        unsigned kbits = (unsigned)(key >> 32);
        float v = __uint_as_float(kbits);
        int kept = (keepw[t >> 5] >> (t & 31)) & 1;
        bool live = kept && v > 0.0f;
        ks[t] = live ? v : 0.0f;
        ki[t] = 0xFFFFFFFFu - (unsigned)(key & 0xFFFFFFFFull);
        if (live) atomicAdd(&g_fhist[b * FH_BINS + fh_bin(kbits)], 1u);
    }
}

// ============================================================
// Kernel 3a: per-image rank-200 threshold from exact histogram.
// 256 threads, histogram staged in smem (coalesced).
// ============================================================
__global__ __launch_bounds__(256) void thresh_kernel()
{
    __shared__ unsigned fh[FH_BINS];
    int tid = threadIdx.x;
    int lane = tid & 31;
    int b = blockIdx.x;

    const uint4* src = (const uint4*)(g_fhist + b * FH_BINS);
    uint4* dst = (uint4*)fh;
    for (int i = tid; i < FH_BINS / 4; i += 256) dst[i] = src[i];
    __syncthreads();

    if (tid < 32) {
        int per = FH_BINS / 32;               // 128 bins per lane
        int hi = FH_BINS - 1 - lane * per;
        unsigned s = 0;
        for (int e = 0; e < per; e++) { int bin = hi - e; if (bin >= 1) s += fh[bin]; }
        unsigned inc = s;
#pragma unroll
        for (int off = 1; off < 32; off <<= 1) {
            unsigned t2 = __shfl_up_sync(0xFFFFFFFFu, inc, off);
            if (lane >= off) inc += t2;
        }
        unsigned excl = inc - s;
        bool has = (excl < (unsigned)MAX_BOXES) && (inc >= (unsigned)MAX_BOXES);
        unsigned ball = __ballot_sync(0xFFFFFFFFu, has);
        if (lane == 0 && ball == 0u) g_final_T[b] = 0u;   // fallback
        if (ball != 0u && lane == (__ffs(ball) - 1)) {
            unsigned T = 0u;
            unsigned cum = excl;
            for (int e = 0; e < per; e++) {
                int bin = hi - e;
                if (bin < 1) break;
                unsigned h = fh[bin];
                if (cum + h >= (unsigned)MAX_BOXES) {
                    if (cum + h <= (unsigned)CAND_CAP)
                        T = 0x3F000000u | ((unsigned)bin << 11);
                    break;
                }
                cum += h;
            }
            g_final_T[b] = T;
        }
    }
}

// ============================================================
// Kernel 3b: parallel per-image compaction of kept scores >= T
// grid = BATCH * FSEG, 256 threads
// ============================================================
__global__ __launch_bounds__(256) void fcompact_kernel()
{
    int tid = threadIdx.x;
    int lane = tid & 31;
    int blk = blockIdx.x;
    int b = blk / FSEG;
    int seg = blk % FSEG;
    unsigned T = g_final_T[b];
    if (T == 0u) return;                      // fallback handled in foutput

    const int n4 = FLAT_K / 4;                // 8000
    const int per = n4 / FSEG;                // 500
    const float4* sc4 = (const float4*)(g_kept_scores + (size_t)b * FLAT_K) + seg * per;
    int ibase = seg * per;

    for (int i = tid; i < per; i += 256) {
        float4 v = sc4[i];
        unsigned kk[4] = {__float_as_uint(v.x), __float_as_uint(v.y),
                          __float_as_uint(v.z), __float_as_uint(v.w)};
        bool tk[4];
#pragma unroll
        for (int e = 0; e < 4; e++) tk[e] = kk[e] >= T;
        int c = (int)tk[0] + (int)tk[1] + (int)tk[2] + (int)tk[3];
        if (__any_sync(0xFFFFFFFFu, c > 0)) {
            int pre = c;
#pragma unroll
            for (int off = 1; off < 32; off <<= 1) {
                int t2 = __shfl_up_sync(0xFFFFFFFFu, pre, off);
                if (lane >= off) pre += t2;
            }
            unsigned base;
            if (lane == 31 && pre > 0) base = atomicAdd(&g_fcand_cnt[b], (unsigned)pre);
            base = __shfl_sync(0xFFFFFFFFu, base, 31);
            unsigned pos = base + (unsigned)(pre - c);
#pragma unroll
            for (int e = 0; e < 4; e++) {
                if (tk[e]) {
                    if (pos < CAND_CAP) {
                        unsigned flat = (unsigned)((ibase + i) * 4 + e);
                        g_fcand[(size_t)b * CAND_CAP + pos] =
                            ((ull)kk[e] << 32) | (ull)(0xFFFFFFFFu - flat);
                    }
                    pos++;
                }
            }
        }
    }
}

// ============================================================
// Kernel 3c: per-image select + sort + output
// grid = BATCH, 256 threads
// out layout (float32): bbox[8][200][4] | conf[8][200] | cls[8][200] | num[8]
// ============================================================
__global__ __launch_bounds__(256) void foutput_kernel(float* __restrict__ out)
{
    __shared__ ull cand[CAND_CAP];            // 16 KB
    __shared__ unsigned shist[2048];          // select_key (1024) / radix fallback (2048)
    __shared__ ull cand2[512];
    __shared__ RadixState rst;
    __shared__ SelState sst;
    __shared__ int s_cnt, s_nval;

    int tid = threadIdx.x;
    int b = blockIdx.x;
    unsigned T = g_final_T[b];
    int cnt;

    if (T != 0u) {
        cnt = min((int)g_fcand_cnt[b], CAND_CAP);
        const ull* src = g_fcand + (size_t)b * CAND_CAP;
        for (int i = tid; i < cnt; i += 256) cand[i] = src[i];
        __syncthreads();
    } else {
        // exact fallback: scan kept scores
        const float4* sc4 = (const float4*)(g_kept_scores + (size_t)b * FLAT_K);
        const int n4 = FLAT_K / 4;
        unsigned Tf = radix_thresh(sc4, n4, MAX_BOXES, 512, shist, &rst);
        cnt = compact_pass(sc4, n4, Tf, cand, 512, &s_cnt);
        cnt = min(cnt, 512);
    }

    ull Tk = 0ull;
    if (cnt > 512)
        Tk = select_key(cand, cnt, MAX_BOXES, 512, shist, &sst);
    cnt = compact_keys(cand, cnt, Tk, cand2, 512, &s_cnt);
    cnt = min(cnt, 512);
    for (int i = tid; i < 512; i += 256) if (i >= cnt) cand2[i] = 0ULL;
    bitonic_desc<512>(cand2);

    if (tid == 0) s_nval = 0;
    __syncthreads();

    const unsigned* ki = g_kept_idx + (size_t)b * FLAT_K;
    const float4* gb4 = (const float4*)g_boxes + (size_t)b * NANCH;
    for (int t = tid; t < MAX_BOXES; t += 256) {
        ull e = cand2[t];
        float v = __uint_as_float((unsigned)(e >> 32));
        bool valid = v > 0.0f;
        unsigned flat = 0xFFFFFFFFu - (unsigned)(e & 0xFFFFFFFFull);
        float4 bb = make_float4(0.f, 0.f, 0.f, 0.f);
        float clsf = 0.f;
        if (valid) {
            bb = gb4[ki[flat]];
            clsf = (float)(flat / PRE_NMS_K);
            atomicAdd(&s_nval, 1);
        }
        int o = b * MAX_BOXES + t;
        ((float4*)out)[o] = bb;
        out[BATCH * MAX_BOXES * 4 + o] = v;
        out[BATCH * MAX_BOXES * 4 + BATCH * MAX_BOXES + o] = clsf;
    }
    __syncthreads();
    if (tid == 0)
        out[BATCH * MAX_BOXES * 4 + 2 * BATCH * MAX_BOXES + b] = (float)s_nval;
}

// ============================================================
extern "C" void kernel_launch(void* const* d_in, const int* in_sizes, int n_in,
                              void* d_out, int out_size)
{
    const float* p3 = (const float*)d_in[0];
    const float* p4 = (const float*)d_in[1];
    const float* p5 = (const float*)d_in[2];
    const float* a3 = (const float*)d_in[3];
    const float* a4 = (const float*)d_in[4];
    const float* a5 = (const float*)d_in[5];
    float* out = (float*)d_out;

    reset_kernel<<<(BATCH * FH_BINS + 255) / 256, 256>>>();
    decode_kernel<<<BATCH * (NANCH / 64), 256>>>(p3, p4, p5, a3, a4, a5);
    percls_kernel<<<BATCH * NUM_CLASSES, 256>>>();
    thresh_kernel<<<BATCH, 256>>>();
    fcompact_kernel<<<BATCH * FSEG, 256>>>();
    foutput_kernel<<<BATCH, 256>>>(out);
}